// round 11
// baseline (speedup 1.0000x reference)
#include <cuda_runtime.h>
#include <cuda_bf16.h>
#include <cstdint>

// Problem constants
#define BB 32
#define SV 4096
#define SQ 1152
#define DD 128
#define FD 96
#define NS 4                  // power sums S1..S4
#define CH 16                 // s-chunks in v pass (R3 proven)
#define ROWS (SV / CH)        // 256 rows per chunk
#define NPOOL (SQ / 12 * DD)  // 12288 pooled 12-sums per batch
#define VBLOCKS (CH * BB)     // 512
#define QB_PER_B 16
#define QBLOCKS (BB * QB_PER_B)            // 512
#define P1BLOCKS (VBLOCKS + QBLOCKS)       // 1024
#define GRID (P1BLOCKS + BB + FD)          // 1152

// Scratch (no allocations allowed)
__device__ float g_part[CH * BB * NS * DD];
__device__ float g_qpool[BB * NPOOL];
__device__ float g_qs[BB * DD];
__device__ float g_att0[BB * DD];
__device__ float g_pI[BB * FD];
__device__ float g_L[BB], g_sa[BB], g_sa2[BB];
__device__ int   g_cb[BB];  // per-batch pass1 completions (16 v + 16 q = 32)
__device__ int   g_done;    // solve completions
__device__ int   g_cfin;    // finisher completions (for reset)

// ---------------------------------------------------------------------------
// ONE kernel, three phases, PER-BATCH dependency gating.
// ---------------------------------------------------------------------------
__global__ void __launch_bounds__(256, 6)
k_all(const float* __restrict__ v, const float* __restrict__ q,
      const float* __restrict__ hmat, const float* __restrict__ hbias,
      const float* __restrict__ gamma, const float* __restrict__ beta,
      float* __restrict__ out) {
    int t = threadIdx.x;
    int bid = blockIdx.x;

    if (bid < VBLOCKS) {
        // ================= v power sums S1..S4 (R3 verbatim) ==================
        int chunk = bid & (CH - 1);
        int b = bid / CH;
        int lane = t & 31, w = t >> 5;
        const float4* vp = (const float4*)(v + ((size_t)b * SV + (size_t)chunk * ROWS) * DD);

        float s1[4] = {0,0,0,0}, s2[4] = {0,0,0,0}, s3[4] = {0,0,0,0}, s4[4] = {0,0,0,0};

        #pragma unroll 8
        for (int i = 0; i < ROWS / 8; i++) {
            int r = w + 8 * i;
            float4 x = vp[r * 32 + lane];
            float xv[4] = {x.x, x.y, x.z, x.w};
            #pragma unroll
            for (int j = 0; j < 4; j++) {
                float a = xv[j];
                float a2 = a * a;
                s1[j] += a;
                s2[j] += a2;
                s3[j] = fmaf(a2, a, s3[j]);
                s4[j] = fmaf(a2, a2, s4[j]);
            }
        }

        __shared__ float sh[8][NS][DD];
        int d0 = lane * 4;
        #pragma unroll
        for (int j = 0; j < 4; j++) {
            sh[w][0][d0 + j] = s1[j];
            sh[w][1][d0 + j] = s2[j];
            sh[w][2][d0 + j] = s3[j];
            sh[w][3][d0 + j] = s4[j];
        }
        __syncthreads();
        #pragma unroll
        for (int idx = t; idx < NS * DD; idx += 256) {
            int k = idx >> 7, d = idx & 127;
            float acc = 0.f;
            #pragma unroll
            for (int ww = 0; ww < 8; ww++) acc += sh[ww][k][d];
            g_part[((chunk * BB + b) * NS + k) * DD + d] = acc;
        }
        // release to THIS batch's counter
        __threadfence();
        __syncthreads();
        if (t == 0) atomicAdd(&g_cb[b], 1);
        return;
    }

    if (bid < P1BLOCKS) {
        // ================= q pooled sums (R3 verbatim) ========================
        int qb = bid - VBLOCKS;
        int b  = qb / QB_PER_B;
        int kg = qb % QB_PER_B;
        const float4* p = (const float4*)(q + (size_t)b * SQ * DD) + (size_t)kg * 2304;
        __shared__ float sp[768];
        #pragma unroll
        for (int j = 0; j < 3; j++) {
            int pidx = t + j * 256;
            const float4* pp = p + pidx * 3;
            float4 a = pp[0], c = pp[1], e = pp[2];
            float s = ((a.x + a.y) + (a.z + a.w))
                    + ((c.x + c.y) + (c.z + c.w))
                    + ((e.x + e.y) + (e.z + e.w));
            sp[pidx] = s;
            g_qpool[(size_t)b * NPOOL + kg * 768 + pidx] = s;
        }
        __syncthreads();
        if (t < 8) {
            float acc = 0.f;
            #pragma unroll
            for (int f = 0; f < 96; f++) acc += sp[t * 96 + f];
            g_qs[b * DD + kg * 8 + t] = acc;
        }
        // release to THIS batch's counter
        __threadfence();
        __syncthreads();
        if (t == 0) atomicAdd(&g_cb[b], 1);
        return;
    }

    if (bid < P1BLOCKS + BB) {
        // ================= SOLVE for batch b (gated on g_cb[b] only) ==========
        int b = bid - P1BLOCKS;
        __shared__ float sS[NS][DD];
        __shared__ float sqs[DD];
        __shared__ float shm[3], shb[3];
        __shared__ float sred[8];
        __shared__ float sred5[8][5];
        __shared__ float spf[2][FD];
        __shared__ float s_sumq;

        // hm/hbias don't depend on pass1 — compute while waiting
        if (t < 3) {
            float a = 0.f;
            for (int x = 0; x < FD; x++) a += hmat[t * FD + x];
            shm[t] = a;
            shb[t] = hbias[t];
        }

        // acquire: only batch b's 32 producer blocks
        if (t == 0) {
            while (*(volatile int*)&g_cb[b] < CH + QB_PER_B) __nanosleep(32);
        }
        __syncthreads();
        __threadfence();

        // a) combine per-chunk partial power sums
        #pragma unroll
        for (int idx = t; idx < NS * DD; idx += 256) {
            int k = idx >> 7, d = idx & 127;
            float acc = 0.f;
            #pragma unroll
            for (int c = 0; c < CH; c++)
                acc += __ldcg(&g_part[((c * BB + b) * NS + k) * DD + d]);
            sS[k][d] = acc;
        }

        // b) qs
        float myqs = 0.f;
        if (t < DD) { myqs = __ldcg(&g_qs[b * DD + t]); sqs[t] = myqs; }
        __syncthreads();

        // sumq
        {
            float val = (t < DD) ? myqs : 0.f;
            #pragma unroll
            for (int o = 16; o; o >>= 1) val += __shfl_down_sync(0xffffffffu, val, o);
            if ((t & 31) == 0) sred[t >> 5] = val;
            __syncthreads();
            if (t == 0) {
                float s = 0.f;
                #pragma unroll
                for (int i = 0; i < 8; i++) s += sred[i];
                s_sumq = s;
            }
            __syncthreads();
        }
        float sumq = s_sumq;

        // d) per-d alpha/Z via Taylor; softmax rows 0..2
        float e0 = 0.f, e1 = 0.f, e2 = 0.f, S1v = 0.f, r2 = 0.f, r3 = 0.f;
        if (t < DD) {
            int d = t;
            float S1 = sS[0][d], S2 = sS[1][d], S3 = sS[2][d], S4 = sS[3][d];
            S1v = S1;
            const float* vb = v + (size_t)b * SV * DD + d;
            float v0 = vb[0], v1 = vb[DD], v2 = vb[2 * DD];
            #pragma unroll
            for (int c = 0; c < 3; c++) {
                float A  = shm[c] * sumq;
                float Bc = shb[c];
                float n2 = A * A * S2 + 2.f * A * Bc * S1 + (float)SV * Bc * Bc;
                float al = A * rsqrtf(n2);
                float Z = (float)SV
                    + al * (S1 + al * (0.5f * S2 + al * ((1.f/6.f) * S3
                    + al * (1.f/24.f) * S4)));
                float iZ = 1.f / Z;
                e0 += __expf(al * v0) * iZ;
                e1 += __expf(al * v1) * iZ;
                e2 += __expf(al * v2) * iZ;
            }
            g_att0[b * DD + t] = e0;
            r2 = e1 * sqs[t];
            r3 = e2 * sqs[t];
        }

        // e) reductions
        {
            float r[5] = {e0, e0 * e0, r2, r3, S1v};
            #pragma unroll
            for (int o = 16; o; o >>= 1) {
                #pragma unroll
                for (int j = 0; j < 5; j++) r[j] += __shfl_down_sync(0xffffffffu, r[j], o);
            }
            if ((t & 31) == 0) {
                #pragma unroll
                for (int j = 0; j < 5; j++) sred5[t >> 5][j] = r[j];
            }
            __syncthreads();
            if (t == 0) {
                float sa = 0.f, sa2 = 0.f, dot1 = 0.f, dot2 = 0.f, vs = 0.f;
                #pragma unroll
                for (int i = 0; i < 8; i++) {
                    sa += sred5[i][0]; sa2 += sred5[i][1];
                    dot1 += sred5[i][2]; dot2 += sred5[i][3];
                    vs += sred5[i][4];
                }
                g_sa[b] = sa;
                g_sa2[b] = sa2;
                g_L[b] = vs * dot1 + vs * dot2;
            }
        }

        // f) pooledInner[b,f], 2-way k-split
        if (t < 2 * FD) {
            int f = t % FD, h = t / FD;
            float acc = 0.f;
            const float* qp = g_qpool + (size_t)b * NPOOL + f + h * 64 * FD;
            #pragma unroll 8
            for (int k = 0; k < 64; k++) acc += sS[0][h * 64 + k] * __ldcg(qp + k * FD);
            spf[h][f] = acc;
        }
        __syncthreads();
        if (t < FD) g_pI[b * FD + t] = (spf[0][t] + spf[1][t]) * (1.f / 12.f);

        // release
        __threadfence();
        __syncthreads();
        if (t == 0) atomicAdd(&g_done, 1);
        return;
    }

    // ================= FINISH for channel f ==================================
    int f = bid - (P1BLOCKS + BB);
    __shared__ float sPI[BB], sL[BB];
    __shared__ float s_scale, s_shift;

    float gam = gamma[f], bet = beta[f];      // prefetch while waiting

    if (t == 0) {
        while (*(volatile int*)&g_done < BB) __nanosleep(32);
    }
    __syncthreads();
    __threadfence();

    float m = 0.f, m2 = 0.f;
    if (t < BB) {
        float pi  = __ldcg(&g_pI[t * FD + f]);
        float L   = __ldcg(&g_L[t]);
        float sa  = __ldcg(&g_sa[t]);
        float sa2 = __ldcg(&g_sa2[t]);
        sPI[t] = pi;
        sL[t]  = L;
        m  = pi * sa + (float)DD * L;
        m2 = pi * pi * sa2 + 2.f * pi * L * sa + (float)DD * L * L;
    }
    if (t < 32) {
        #pragma unroll
        for (int o = 16; o; o >>= 1) {
            m  += __shfl_down_sync(0xffffffffu, m,  o);
            m2 += __shfl_down_sync(0xffffffffu, m2, o);
        }
        if (t == 0) {
            const float inv = 1.f / (float)(BB * DD);
            float mean = m * inv;
            float var  = m2 * inv - mean * mean;
            float scale = gam * rsqrtf(var + 1e-5f);
            s_scale = scale;
            s_shift = bet - mean * scale;
        }
    }
    __syncthreads();
    float scale = s_scale, shift = s_shift;

    if (t < DD) {
        int d = t;
        #pragma unroll 8
        for (int b = 0; b < BB; b++) {
            float val = __ldcg(&g_att0[b * DD + d]) * sPI[b] + sL[b];
            out[((size_t)b * FD + f) * DD + d] = val * scale + shift;
        }
    }

    // last finisher resets counters for the next graph replay
    __threadfence();
    __syncthreads();
    if (t == 0) {
        int r = atomicAdd(&g_cfin, 1);
        if (r == FD - 1) {
            #pragma unroll
            for (int b = 0; b < BB; b++) g_cb[b] = 0;
            g_done = 0;
            g_cfin = 0;
            __threadfence();
        }
    }
}

extern "C" void kernel_launch(void* const* d_in, const int* in_sizes, int n_in,
                              void* d_out, int out_size) {
    const float* q     = (const float*)d_in[0];
    const float* v     = (const float*)d_in[1];
    const float* hmat  = (const float*)d_in[2];
    const float* hbias = (const float*)d_in[3];
    const float* gamma = (const float*)d_in[4];
    const float* beta  = (const float*)d_in[5];
    float* out = (float*)d_out;

    k_all<<<GRID, 256>>>(v, q, hmat, hbias, gamma, beta, out);
}

// round 12
// speedup vs baseline: 1.0559x; 1.0559x over previous
#include <cuda_runtime.h>
#include <cuda_bf16.h>
#include <cstdint>

// Problem constants
#define BB 32
#define SV 4096
#define SQ 1152
#define DD 128
#define FD 96
#define NS 4                  // power sums S1..S4
#define CH 16                 // s-chunks in v pass (proven)
#define ROWS (SV / CH)        // 256 rows per chunk
#define NPOOL (SQ / 12 * DD)  // 12288 pooled 12-sums per batch
#define VBLOCKS (CH * BB)     // 512
#define QB_PER_B 8            // q blocks per batch; each owns 2 kg-groups = 16 k-rows
#define QBLOCKS (BB * QB_PER_B)   // 256
#define P1GRID (VBLOCKS + QBLOCKS) // 768  -> single wave (<= 888 slots)

// Scratch (no allocations allowed)
__device__ float g_part[CH * BB * NS * DD];
__device__ float g_qpool[BB * NPOOL];
__device__ float g_qs[BB * DD];
__device__ float g_att0[BB * DD];
__device__ float g_pI[BB * FD];
__device__ float g_L[BB], g_sa[BB], g_sa2[BB];
__device__ int   g_done;

// ---------------------------------------------------------------------------
// K1: single-wave pass1. 512 v-blocks (R3 body) + 256 double-width q-blocks.
// ---------------------------------------------------------------------------
__global__ void __launch_bounds__(256, 6)
k_pass1(const float* __restrict__ v, const float* __restrict__ q) {
    int t = threadIdx.x;

    if (blockIdx.x == 0 && t == 0) g_done = 0;   // reset flag for k_tail

    if (blockIdx.x >= VBLOCKS) {
        // ---- q part: TWO kg-groups (16 complete k-rows, 73.7KB) ----
        int qb = blockIdx.x - VBLOCKS;
        int b   = qb / QB_PER_B;
        int kg0 = (qb % QB_PER_B) * 2;
        __shared__ float sp[768];
        #pragma unroll
        for (int g = 0; g < 2; g++) {
            int kg = kg0 + g;
            const float4* p = (const float4*)(q + (size_t)b * SQ * DD) + (size_t)kg * 2304;
            #pragma unroll
            for (int j = 0; j < 3; j++) {
                int pidx = t + j * 256;
                const float4* pp = p + pidx * 3;
                float4 a = pp[0], c = pp[1], e = pp[2];
                float s = ((a.x + a.y) + (a.z + a.w))
                        + ((c.x + c.y) + (c.z + c.w))
                        + ((e.x + e.y) + (e.z + e.w));
                sp[pidx] = s;
                g_qpool[(size_t)b * NPOOL + kg * 768 + pidx] = s;
            }
            __syncthreads();
            if (t < 8) {
                float acc = 0.f;
                #pragma unroll
                for (int f = 0; f < 96; f++) acc += sp[t * 96 + f];
                g_qs[b * DD + kg * 8 + t] = acc;
            }
            __syncthreads();
        }
        return;
    }

    // ---- v power sums S1..S4 (R3 verbatim) ----
    int chunk = blockIdx.x & (CH - 1);
    int b = blockIdx.x / CH;
    int lane = t & 31, w = t >> 5;
    const float4* vp = (const float4*)(v + ((size_t)b * SV + (size_t)chunk * ROWS) * DD);

    float s1[4] = {0,0,0,0}, s2[4] = {0,0,0,0}, s3[4] = {0,0,0,0}, s4[4] = {0,0,0,0};

    #pragma unroll 8
    for (int i = 0; i < ROWS / 8; i++) {
        int r = w + 8 * i;
        float4 x = vp[r * 32 + lane];
        float xv[4] = {x.x, x.y, x.z, x.w};
        #pragma unroll
        for (int j = 0; j < 4; j++) {
            float a = xv[j];
            float a2 = a * a;
            s1[j] += a;
            s2[j] += a2;
            s3[j] = fmaf(a2, a, s3[j]);
            s4[j] = fmaf(a2, a2, s4[j]);
        }
    }

    __shared__ float sh[8][NS][DD];
    int d0 = lane * 4;
    #pragma unroll
    for (int j = 0; j < 4; j++) {
        sh[w][0][d0 + j] = s1[j];
        sh[w][1][d0 + j] = s2[j];
        sh[w][2][d0 + j] = s3[j];
        sh[w][3][d0 + j] = s4[j];
    }
    __syncthreads();
    #pragma unroll
    for (int idx = t; idx < NS * DD; idx += 256) {
        int k = idx >> 7, d = idx & 127;
        float acc = 0.f;
        #pragma unroll
        for (int ww = 0; ww < 8; ww++) acc += sh[ww][k][d];
        g_part[((chunk * BB + b) * NS + k) * DD + d] = acc;
    }
}

// ---------------------------------------------------------------------------
// K2: fused solve + finish (R6 proven verbatim).
// ---------------------------------------------------------------------------
__global__ void k_tail(const float* __restrict__ v,
                       const float* __restrict__ hmat,
                       const float* __restrict__ hbias,
                       const float* __restrict__ gamma,
                       const float* __restrict__ beta,
                       float* __restrict__ out) {
    int t = threadIdx.x;

    if (blockIdx.x < BB) {
        // ================= SOLVE for batch b =================
        int b = blockIdx.x;
        __shared__ float sS[NS][DD];
        __shared__ float sqs[DD];
        __shared__ float shm[3], shb[3];
        __shared__ float sred[8];
        __shared__ float sred5[8][5];
        __shared__ float spf[2][FD];
        __shared__ float s_sumq;

        // a) combine per-chunk partial power sums
        #pragma unroll
        for (int idx = t; idx < NS * DD; idx += 256) {
            int k = idx >> 7, d = idx & 127;
            float acc = 0.f;
            #pragma unroll
            for (int c = 0; c < CH; c++)
                acc += g_part[((c * BB + b) * NS + k) * DD + d];
            sS[k][d] = acc;
        }

        // b) qs from g_qs
        float myqs = 0.f;
        if (t < DD) { myqs = g_qs[b * DD + t]; sqs[t] = myqs; }

        // c) hm[c], hbias[c]
        if (t < 3) {
            float a = 0.f;
            for (int x = 0; x < FD; x++) a += hmat[t * FD + x];
            shm[t] = a;
            shb[t] = hbias[t];
        }
        __syncthreads();

        // sumq
        {
            float val = (t < DD) ? myqs : 0.f;
            #pragma unroll
            for (int o = 16; o; o >>= 1) val += __shfl_down_sync(0xffffffffu, val, o);
            if ((t & 31) == 0) sred[t >> 5] = val;
            __syncthreads();
            if (t == 0) {
                float s = 0.f;
                #pragma unroll
                for (int i = 0; i < 8; i++) s += sred[i];
                s_sumq = s;
            }
            __syncthreads();
        }
        float sumq = s_sumq;

        // d) per-d alpha/Z via Taylor (S1..S4); softmax rows 0..2
        float e0 = 0.f, e1 = 0.f, e2 = 0.f, S1v = 0.f, r2 = 0.f, r3 = 0.f;
        if (t < DD) {
            int d = t;
            float S1 = sS[0][d], S2 = sS[1][d], S3 = sS[2][d], S4 = sS[3][d];
            S1v = S1;
            const float* vb = v + (size_t)b * SV * DD + d;
            float v0 = vb[0], v1 = vb[DD], v2 = vb[2 * DD];
            #pragma unroll
            for (int c = 0; c < 3; c++) {
                float A  = shm[c] * sumq;
                float Bc = shb[c];
                float n2 = A * A * S2 + 2.f * A * Bc * S1 + (float)SV * Bc * Bc;
                float al = A * rsqrtf(n2);
                float Z = (float)SV
                    + al * (S1 + al * (0.5f * S2 + al * ((1.f/6.f) * S3
                    + al * (1.f/24.f) * S4)));
                float iZ = 1.f / Z;
                e0 += __expf(al * v0) * iZ;
                e1 += __expf(al * v1) * iZ;
                e2 += __expf(al * v2) * iZ;
            }
            g_att0[b * DD + t] = e0;
            r2 = e1 * sqs[t];
            r3 = e2 * sqs[t];
        }

        // e) reductions
        {
            float r[5] = {e0, e0 * e0, r2, r3, S1v};
            #pragma unroll
            for (int o = 16; o; o >>= 1) {
                #pragma unroll
                for (int j = 0; j < 5; j++) r[j] += __shfl_down_sync(0xffffffffu, r[j], o);
            }
            if ((t & 31) == 0) {
                #pragma unroll
                for (int j = 0; j < 5; j++) sred5[t >> 5][j] = r[j];
            }
            __syncthreads();
            if (t == 0) {
                float sa = 0.f, sa2 = 0.f, dot1 = 0.f, dot2 = 0.f, vs = 0.f;
                #pragma unroll
                for (int i = 0; i < 8; i++) {
                    sa += sred5[i][0]; sa2 += sred5[i][1];
                    dot1 += sred5[i][2]; dot2 += sred5[i][3];
                    vs += sred5[i][4];
                }
                g_sa[b] = sa;
                g_sa2[b] = sa2;
                g_L[b] = vs * dot1 + vs * dot2;
            }
        }

        // f) pooledInner[b,f], 2-way k-split
        if (t < 2 * FD) {
            int f = t % FD, h = t / FD;
            float acc = 0.f;
            const float* qp = g_qpool + (size_t)b * NPOOL + f + h * 64 * FD;
            #pragma unroll 8
            for (int k = 0; k < 64; k++) acc += sS[0][h * 64 + k] * qp[k * FD];
            spf[h][f] = acc;
        }
        __syncthreads();
        if (t < FD) g_pI[b * FD + t] = (spf[0][t] + spf[1][t]) * (1.f / 12.f);

        // release
        __threadfence();
        __syncthreads();
        if (t == 0) atomicAdd(&g_done, 1);
        return;
    }

    // ================= FINISH for channel f =================
    int f = blockIdx.x - BB;
    __shared__ float sPI[BB], sL[BB];
    __shared__ float s_scale, s_shift;

    float gam = gamma[f], bet = beta[f];      // prefetch while waiting

    if (t == 0) {
        while (*(volatile int*)&g_done < BB) __nanosleep(64);
    }
    __syncthreads();
    __threadfence();

    float m = 0.f, m2 = 0.f;
    if (t < BB) {
        float pi  = __ldcg(&g_pI[t * FD + f]);
        float L   = __ldcg(&g_L[t]);
        float sa  = __ldcg(&g_sa[t]);
        float sa2 = __ldcg(&g_sa2[t]);
        sPI[t] = pi;
        sL[t]  = L;
        m  = pi * sa + (float)DD * L;
        m2 = pi * pi * sa2 + 2.f * pi * L * sa + (float)DD * L * L;
    }
    if (t < 32) {
        #pragma unroll
        for (int o = 16; o; o >>= 1) {
            m  += __shfl_down_sync(0xffffffffu, m,  o);
            m2 += __shfl_down_sync(0xffffffffu, m2, o);
        }
        if (t == 0) {
            const float inv = 1.f / (float)(BB * DD);
            float mean = m * inv;
            float var  = m2 * inv - mean * mean;
            float scale = gam * rsqrtf(var + 1e-5f);
            s_scale = scale;
            s_shift = bet - mean * scale;
        }
    }
    __syncthreads();
    float scale = s_scale, shift = s_shift;

    if (t < DD) {
        int d = t;
        #pragma unroll 8
        for (int b = 0; b < BB; b++) {
            float val = __ldcg(&g_att0[b * DD + d]) * sPI[b] + sL[b];
            out[((size_t)b * FD + f) * DD + d] = val * scale + shift;
        }
    }
}

extern "C" void kernel_launch(void* const* d_in, const int* in_sizes, int n_in,
                              void* d_out, int out_size) {
    const float* q     = (const float*)d_in[0];
    const float* v     = (const float*)d_in[1];
    const float* hmat  = (const float*)d_in[2];
    const float* hbias = (const float*)d_in[3];
    const float* gamma = (const float*)d_in[4];
    const float* beta  = (const float*)d_in[5];
    float* out = (float*)d_out;

    k_pass1<<<P1GRID, 256>>>(v, q);
    k_tail<<<BB + FD, 256>>>(v, hmat, hbias, gamma, beta, out);
}

// round 13
// speedup vs baseline: 1.0571x; 1.0011x over previous
#include <cuda_runtime.h>
#include <cuda_bf16.h>
#include <cstdint>

// Problem constants
#define BB 32
#define SV 4096
#define SQ 1152
#define DD 128
#define FD 96
#define NS 4                  // power sums S1..S4
#define CH 16                 // s-chunks in v pass (proven)
#define ROWS (SV / CH)        // 256 rows per chunk
#define NPOOL (SQ / 12 * DD)  // 12288 pooled 12-sums per batch
#define VBLOCKS (CH * BB)     // 512
#define QB_PER_B 8            // q blocks per batch; each owns 2 kg-groups
#define QBLOCKS (BB * QB_PER_B)    // 256
#define P1GRID (VBLOCKS + QBLOCKS) // 768 -> single wave
#define NPROD (CH + QB_PER_B)      // 24 producers per batch

// Scratch (no allocations allowed)
__device__ float g_part[CH * BB * NS * DD];
__device__ float g_qpool[BB * NPOOL];
__device__ float g_qs[BB * DD];
__device__ float g_att0[BB * DD];
__device__ float g_pI[BB * FD];
__device__ float g_L[BB], g_sa[BB], g_sa2[BB];
__device__ int   g_cb[BB];   // per-batch producer completions (reset by k_tail)

// ---------------------------------------------------------------------------
// K1: pass1 + inline per-batch solve (executed by the LAST producer block
//     of each batch, threadfence-reduction style).
// ---------------------------------------------------------------------------
__global__ void __launch_bounds__(256, 6)
k_pass1(const float* __restrict__ v, const float* __restrict__ q,
        const float* __restrict__ hmat, const float* __restrict__ hbias) {
    int t = threadIdx.x;
    int b;

    if (blockIdx.x >= VBLOCKS) {
        // ---- q part: TWO kg-groups (16 complete k-rows) ----
        int qb = blockIdx.x - VBLOCKS;
        b = qb / QB_PER_B;
        int kg0 = (qb % QB_PER_B) * 2;
        __shared__ float sp[768];
        #pragma unroll
        for (int g = 0; g < 2; g++) {
            int kg = kg0 + g;
            const float4* p = (const float4*)(q + (size_t)b * SQ * DD) + (size_t)kg * 2304;
            #pragma unroll
            for (int j = 0; j < 3; j++) {
                int pidx = t + j * 256;
                const float4* pp = p + pidx * 3;
                float4 a = pp[0], c = pp[1], e = pp[2];
                float s = ((a.x + a.y) + (a.z + a.w))
                        + ((c.x + c.y) + (c.z + c.w))
                        + ((e.x + e.y) + (e.z + e.w));
                sp[pidx] = s;
                g_qpool[(size_t)b * NPOOL + kg * 768 + pidx] = s;
            }
            __syncthreads();
            if (t < 8) {
                float acc = 0.f;
                #pragma unroll
                for (int f = 0; f < 96; f++) acc += sp[t * 96 + f];
                g_qs[b * DD + kg * 8 + t] = acc;
            }
            __syncthreads();
        }
    } else {
        // ---- v power sums S1..S4 (R3 verbatim) ----
        int chunk = blockIdx.x & (CH - 1);
        b = blockIdx.x / CH;
        int lane = t & 31, w = t >> 5;
        const float4* vp = (const float4*)(v + ((size_t)b * SV + (size_t)chunk * ROWS) * DD);

        float s1[4] = {0,0,0,0}, s2[4] = {0,0,0,0}, s3[4] = {0,0,0,0}, s4[4] = {0,0,0,0};

        #pragma unroll 8
        for (int i = 0; i < ROWS / 8; i++) {
            int r = w + 8 * i;
            float4 x = vp[r * 32 + lane];
            float xv[4] = {x.x, x.y, x.z, x.w};
            #pragma unroll
            for (int j = 0; j < 4; j++) {
                float a = xv[j];
                float a2 = a * a;
                s1[j] += a;
                s2[j] += a2;
                s3[j] = fmaf(a2, a, s3[j]);
                s4[j] = fmaf(a2, a2, s4[j]);
            }
        }

        __shared__ float sh[8][NS][DD];
        int d0 = lane * 4;
        #pragma unroll
        for (int j = 0; j < 4; j++) {
            sh[w][0][d0 + j] = s1[j];
            sh[w][1][d0 + j] = s2[j];
            sh[w][2][d0 + j] = s3[j];
            sh[w][3][d0 + j] = s4[j];
        }
        __syncthreads();
        #pragma unroll
        for (int idx = t; idx < NS * DD; idx += 256) {
            int k = idx >> 7, d = idx & 127;
            float acc = 0.f;
            #pragma unroll
            for (int ww = 0; ww < 8; ww++) acc += sh[ww][k][d];
            g_part[((chunk * BB + b) * NS + k) * DD + d] = acc;
        }
    }

    // ---- ticket: last producer of batch b runs the solve inline ----
    __shared__ int s_last;
    __threadfence();
    __syncthreads();
    if (t == 0) s_last = (atomicAdd(&g_cb[b], 1) == NPROD - 1) ? 1 : 0;
    __syncthreads();
    if (!s_last) return;
    __threadfence();   // all 24 producers' stores are now visible (L2)

    // ================= SOLVE for batch b (R12 math verbatim, __ldcg reads) ===
    {
        __shared__ float sS[NS][DD];
        __shared__ float sqs[DD];
        __shared__ float shm[3], shb[3];
        __shared__ float sred[8];
        __shared__ float sred5[8][5];
        __shared__ float spf[2][FD];
        __shared__ float s_sumq;

        // a) combine per-chunk partial power sums
        #pragma unroll
        for (int idx = t; idx < NS * DD; idx += 256) {
            int k = idx >> 7, d = idx & 127;
            float acc = 0.f;
            #pragma unroll
            for (int c = 0; c < CH; c++)
                acc += __ldcg(&g_part[((c * BB + b) * NS + k) * DD + d]);
            sS[k][d] = acc;
        }

        // b) qs
        float myqs = 0.f;
        if (t < DD) { myqs = __ldcg(&g_qs[b * DD + t]); sqs[t] = myqs; }

        // c) hm[c], hbias[c]
        if (t < 3) {
            float a = 0.f;
            for (int x = 0; x < FD; x++) a += hmat[t * FD + x];
            shm[t] = a;
            shb[t] = hbias[t];
        }
        __syncthreads();

        // sumq
        {
            float val = (t < DD) ? myqs : 0.f;
            #pragma unroll
            for (int o = 16; o; o >>= 1) val += __shfl_down_sync(0xffffffffu, val, o);
            if ((t & 31) == 0) sred[t >> 5] = val;
            __syncthreads();
            if (t == 0) {
                float s = 0.f;
                #pragma unroll
                for (int i = 0; i < 8; i++) s += sred[i];
                s_sumq = s;
            }
            __syncthreads();
        }
        float sumq = s_sumq;

        // d) per-d alpha/Z via Taylor (S1..S4); softmax rows 0..2
        float e0 = 0.f, e1 = 0.f, e2 = 0.f, S1v = 0.f, r2 = 0.f, r3 = 0.f;
        if (t < DD) {
            int d = t;
            float S1 = sS[0][d], S2 = sS[1][d], S3 = sS[2][d], S4 = sS[3][d];
            S1v = S1;
            const float* vb = v + (size_t)b * SV * DD + d;
            float v0 = vb[0], v1 = vb[DD], v2 = vb[2 * DD];
            #pragma unroll
            for (int c = 0; c < 3; c++) {
                float A  = shm[c] * sumq;
                float Bc = shb[c];
                float n2 = A * A * S2 + 2.f * A * Bc * S1 + (float)SV * Bc * Bc;
                float al = A * rsqrtf(n2);
                float Z = (float)SV
                    + al * (S1 + al * (0.5f * S2 + al * ((1.f/6.f) * S3
                    + al * (1.f/24.f) * S4)));
                float iZ = 1.f / Z;
                e0 += __expf(al * v0) * iZ;
                e1 += __expf(al * v1) * iZ;
                e2 += __expf(al * v2) * iZ;
            }
            g_att0[b * DD + t] = e0;
            r2 = e1 * sqs[t];
            r3 = e2 * sqs[t];
        }

        // e) reductions
        {
            float r[5] = {e0, e0 * e0, r2, r3, S1v};
            #pragma unroll
            for (int o = 16; o; o >>= 1) {
                #pragma unroll
                for (int j = 0; j < 5; j++) r[j] += __shfl_down_sync(0xffffffffu, r[j], o);
            }
            if ((t & 31) == 0) {
                #pragma unroll
                for (int j = 0; j < 5; j++) sred5[t >> 5][j] = r[j];
            }
            __syncthreads();
            if (t == 0) {
                float sa = 0.f, sa2 = 0.f, dot1 = 0.f, dot2 = 0.f, vs = 0.f;
                #pragma unroll
                for (int i = 0; i < 8; i++) {
                    sa += sred5[i][0]; sa2 += sred5[i][1];
                    dot1 += sred5[i][2]; dot2 += sred5[i][3];
                    vs += sred5[i][4];
                }
                g_sa[b] = sa;
                g_sa2[b] = sa2;
                g_L[b] = vs * dot1 + vs * dot2;
            }
        }

        // f) pooledInner[b,f], 2-way k-split
        if (t < 2 * FD) {
            int f = t % FD, h = t / FD;
            float acc = 0.f;
            const float* qp = g_qpool + (size_t)b * NPOOL + f + h * 64 * FD;
            #pragma unroll 8
            for (int k = 0; k < 64; k++) acc += sS[0][h * 64 + k] * __ldcg(qp + k * FD);
            spf[h][f] = acc;
        }
        __syncthreads();
        if (t < FD) g_pI[b * FD + t] = (spf[0][t] + spf[1][t]) * (1.f / 12.f);
    }
}

// ---------------------------------------------------------------------------
// K2: finish only (96 blocks). Kernel boundary IS the sync — no spinning.
//     Block 0 also resets the per-batch counters for the next replay.
// ---------------------------------------------------------------------------
__global__ void k_tail(const float* __restrict__ gamma,
                       const float* __restrict__ beta,
                       float* __restrict__ out) {
    int f = blockIdx.x;
    int t = threadIdx.x;

    __shared__ float sPI[BB], sL[BB];
    __shared__ float s_scale, s_shift;

    if (f == 0 && t < BB) g_cb[t] = 0;   // reset for next graph replay

    float m = 0.f, m2 = 0.f;
    if (t < BB) {
        float pi  = g_pI[t * FD + f];
        float L   = g_L[t];
        float sa  = g_sa[t];
        float sa2 = g_sa2[t];
        sPI[t] = pi;
        sL[t]  = L;
        m  = pi * sa + (float)DD * L;
        m2 = pi * pi * sa2 + 2.f * pi * L * sa + (float)DD * L * L;
    }
    if (t < 32) {
        #pragma unroll
        for (int o = 16; o; o >>= 1) {
            m  += __shfl_down_sync(0xffffffffu, m,  o);
            m2 += __shfl_down_sync(0xffffffffu, m2, o);
        }
        if (t == 0) {
            const float inv = 1.f / (float)(BB * DD);
            float mean = m * inv;
            float var  = m2 * inv - mean * mean;
            float scale = gamma[f] * rsqrtf(var + 1e-5f);
            s_scale = scale;
            s_shift = beta[f] - mean * scale;
        }
    }
    __syncthreads();
    float scale = s_scale, shift = s_shift;

    if (t < DD) {
        int d = t;
        #pragma unroll 8
        for (int b = 0; b < BB; b++) {
            float val = g_att0[b * DD + d] * sPI[b] + sL[b];
            out[((size_t)b * FD + f) * DD + d] = val * scale + shift;
        }
    }
}

extern "C" void kernel_launch(void* const* d_in, const int* in_sizes, int n_in,
                              void* d_out, int out_size) {
    const float* q     = (const float*)d_in[0];
    const float* v     = (const float*)d_in[1];
    const float* hmat  = (const float*)d_in[2];
    const float* hbias = (const float*)d_in[3];
    const float* gamma = (const float*)d_in[4];
    const float* beta  = (const float*)d_in[5];
    float* out = (float*)d_out;

    k_pass1<<<P1GRID, 256>>>(v, q, hmat, hbias);
    k_tail<<<FD, 128>>>(gamma, beta, out);
}